// round 2
// baseline (speedup 1.0000x reference)
#include <cuda_runtime.h>
#include <math.h>

// ---------------------------------------------------------------------------
// PowerIterationConv: sigma via Gram iteration, computed in the DFT domain.
//
//   K0: (192,192,3,3).  A(w)[o,a] = sum_s K0[o,a,s] e^{-i w.s}  (w on 17x17 grid)
//   M1(w) = A^H A.  Needed:  f0 = ||K0||_F,
//      n1 = sum_w ||M1||_F^2,  n2 = sum_w ||M1^2||_F^2,  n4 = sum_w ||M1^4||_F^2
//   (Parseval: these equal N^2 * spatial Frobenius norms of the gram chain.)
//   With A pre-scaled by sqrt(SC2)/f0:
//      f1 = sqrt(m1/N^2)/SC2
//      f2 = sqrt(m2/N^2)/(SC2^2 f1^2)
//      ff = sqrt(m4/N^2)/(SC2^4 f1^4 f2^2)
//      sigma = f0 * f1^(1/2) * f2^(1/4) * ff^(1/8);   out = K0 / sigma
// ---------------------------------------------------------------------------

#define CDIM 192
#define MAT (CDIM*CDIM)          // 36864
#define NW 145                   // unique frequencies (conjugate symmetry)
#define NTOT2 289.0              // 17*17
#define SC2 48.0                 // pre-scale^2 applied to A (keeps eigs ~O(1))
#define NPART 1305               // 9 tiles * 145 freqs per gram stage

__device__ double g_f0sq;
__device__ double g_part[3][NPART];
__device__ double g_inv_sigma;
__device__ float2 g_bufA[NW * MAT];   // A, then G2
__device__ float2 g_bufB[NW * MAT];   // G1, then G4

// ---- ||K0||_F^2, single block (deterministic) ------------------------------
__global__ void k_f0(const float* __restrict__ K0, int n) {
    __shared__ double sred[1024];
    double s = 0.0;
    for (int i = threadIdx.x; i < n; i += 1024) {
        float v = K0[i];
        s += (double)v * (double)v;
    }
    sred[threadIdx.x] = s;
    __syncthreads();
    for (int off = 512; off > 0; off >>= 1) {
        if (threadIdx.x < off) sred[threadIdx.x] += sred[threadIdx.x + off];
        __syncthreads();
    }
    if (threadIdx.x == 0) g_f0sq = sred[0];
}

// ---- Build A(w) = DFT of K0, scaled by sqrt(SC2)/f0 ------------------------
// grid (144, 145), block 256. blockIdx.y = frequency index.
__global__ void k_build(const float* __restrict__ K0) {
    int w = blockIdx.y;
    __shared__ float2 ph[9];
    if (threadIdx.x < 9) {
        int u, v;
        if (w == 0)      { u = 0; v = 0; }
        else if (w <= 8) { u = 0; v = w; }
        else             { u = 1 + (w - 9) / 17; v = (w - 9) % 17; }
        int y = threadIdx.x / 3, x = threadIdx.x % 3;
        int m = (u * y + v * x) % 17;
        double ang = -2.0 * 3.14159265358979323846 * (double)m / 17.0;
        double sc = sqrt(SC2 / g_f0sq);
        ph[threadIdx.x] = make_float2((float)(cos(ang) * sc),
                                      (float)(sin(ang) * sc));
    }
    __syncthreads();
    int idx = blockIdx.x * 256 + threadIdx.x;      // (o,a) pair, 0..36863
    const float* kp = K0 + idx * 9;
    float re = 0.f, im = 0.f;
#pragma unroll
    for (int s = 0; s < 9; s++) {
        float k = kp[s];
        re = fmaf(k, ph[s].x, re);
        im = fmaf(k, ph[s].y, im);
    }
    g_bufA[w * MAT + idx] = make_float2(re, im);
}

// ---- Batched gram GEMM: Y = X^H X (192x192 complex per freq) --------------
// stage 0: A->G1 (bufA->bufB), 1: G1->G2 (bufB->bufA), 2: G2->G4 (bufA->bufB)
// Also accumulates weighted ||Y||_F^2 per block into g_part[stage][..].
// grid (3, 3, 145), block 256. 64x64 complex tile, 4x4 complex per thread.
__global__ void k_gram(int stage) {
    const float2* __restrict__ src = (stage == 1) ? g_bufB : g_bufA;
    float2* __restrict__ dst       = (stage == 1) ? g_bufA : g_bufB;

    int w = blockIdx.z;
    const float2* X = src + w * MAT;
    float2* Y       = dst + w * MAT;

    __shared__ float2 sA[16][64];
    __shared__ float2 sB[16][64];

    int tx = threadIdx.x & 15;
    int ty = (threadIdx.x >> 4) & 15;
    int a0 = blockIdx.y * 64;
    int b0 = blockIdx.x * 64;

    float accR[4][4];
    float accI[4][4];
#pragma unroll
    for (int i = 0; i < 4; i++)
#pragma unroll
        for (int j = 0; j < 4; j++) { accR[i][j] = 0.f; accI[i][j] = 0.f; }

    int lc = threadIdx.x & 63;        // load col 0..63
    int lr = threadIdx.x >> 6;        // load row base 0..3

    for (int kc = 0; kc < CDIM; kc += 16) {
#pragma unroll
        for (int rr = 0; rr < 4; rr++) {
            int r = lr + rr * 4;
            sA[r][lc] = X[(kc + r) * CDIM + a0 + lc];
            sB[r][lc] = X[(kc + r) * CDIM + b0 + lc];
        }
        __syncthreads();
#pragma unroll
        for (int kk = 0; kk < 16; kk++) {
            float2 af[4], bf[4];
#pragma unroll
            for (int i = 0; i < 4; i++) af[i] = sA[kk][ty + 16 * i];
#pragma unroll
            for (int j = 0; j < 4; j++) bf[j] = sB[kk][tx + 16 * j];
#pragma unroll
            for (int i = 0; i < 4; i++)
#pragma unroll
                for (int j = 0; j < 4; j++) {
                    // conj(a) * b
                    accR[i][j] = fmaf(af[i].x, bf[j].x, accR[i][j]);
                    accR[i][j] = fmaf(af[i].y, bf[j].y, accR[i][j]);
                    accI[i][j] = fmaf(af[i].x, bf[j].y, accI[i][j]);
                    accI[i][j] = fmaf(-af[i].y, bf[j].x, accI[i][j]);
                }
        }
        __syncthreads();
    }

    float ns = 0.f;
#pragma unroll
    for (int i = 0; i < 4; i++)
#pragma unroll
        for (int j = 0; j < 4; j++) {
            float r = accR[i][j], im = accI[i][j];
            ns = fmaf(r, r, ns);
            ns = fmaf(im, im, ns);
            Y[(a0 + ty + 16 * i) * CDIM + b0 + tx + 16 * j] = make_float2(r, im);
        }

    __shared__ double sred[256];
    sred[threadIdx.x] = (double)ns;
    __syncthreads();
    for (int off = 128; off > 0; off >>= 1) {
        if (threadIdx.x < off) sred[threadIdx.x] += sred[threadIdx.x + off];
        __syncthreads();
    }
    if (threadIdx.x == 0) {
        double wgt = (w == 0) ? 1.0 : 2.0;   // conjugate-pair weight
        g_part[stage][w * 9 + blockIdx.y * 3 + blockIdx.x] = wgt * sred[0];
    }
}

// ---- Deterministic final reduction + sigma ---------------------------------
__global__ void k_sigma() {
    __shared__ double sred[256];
    double m[3];
    for (int s = 0; s < 3; s++) {
        double acc = 0.0;
        for (int i = threadIdx.x; i < NPART; i += 256) acc += g_part[s][i];
        sred[threadIdx.x] = acc;
        __syncthreads();
        for (int off = 128; off > 0; off >>= 1) {
            if (threadIdx.x < off) sred[threadIdx.x] += sred[threadIdx.x + off];
            __syncthreads();
        }
        m[s] = sred[0];
        __syncthreads();
    }
    if (threadIdx.x == 0) {
        double f0 = sqrt(g_f0sq);
        double f1 = sqrt(m[0] / NTOT2) / SC2;
        double f2 = sqrt(m[1] / NTOT2) / (SC2 * SC2 * f1 * f1);
        double ff = sqrt(m[2] / NTOT2) /
                    (SC2 * SC2 * SC2 * SC2 * f1 * f1 * f1 * f1 * f2 * f2);
        double logs = log(f0) + 0.5 * log(f1) + 0.25 * log(f2) + 0.125 * log(ff);
        g_inv_sigma = exp(-logs);
    }
}

__global__ void k_scale(const float* __restrict__ K0, float* __restrict__ out,
                        int n) {
    float s = (float)g_inv_sigma;
    int i = blockIdx.x * 256 + threadIdx.x;
    if (i < n) out[i] = K0[i] * s;
}

extern "C" void kernel_launch(void* const* d_in, const int* in_sizes, int n_in,
                              void* d_out, int out_size) {
    const float* K0 = (const float*)d_in[0];
    float* out = (float*)d_out;
    int n = in_sizes[0];   // 331776

    k_f0<<<1, 1024>>>(K0, n);
    k_build<<<dim3(144, NW), 256>>>(K0);
    k_gram<<<dim3(3, 3, NW), 256>>>(0);
    k_gram<<<dim3(3, 3, NW), 256>>>(1);
    k_gram<<<dim3(3, 3, NW), 256>>>(2);
    k_sigma<<<1, 256>>>();
    k_scale<<<(n + 255) / 256, 256>>>(K0, out, n);
}

// round 3
// speedup vs baseline: 1.6832x; 1.6832x over previous
#include <cuda_runtime.h>
#include <math.h>

// ---------------------------------------------------------------------------
// PowerIterationConv: sigma via Gram iteration, computed in the DFT domain.
//
//   K0: (192,192,3,3).  A(w)[o,a] = sum_s K0[o,a,s] e^{-i w.s}  (w on 17x17 grid)
//   M1(w) = A^H A.  Needed:  f0 = ||K0||_F,
//      n1 = sum_w ||M1||_F^2,  n2 = sum_w ||M1^2||_F^2,  n4 = sum_w ||M1^4||_F^2
//   With A pre-scaled by sqrt(SC2)/f0:
//      f1 = sqrt(m1/N^2)/SC2
//      f2 = sqrt(m2/N^2)/(SC2^2 f1^2)
//      ff = sqrt(m4/N^2)/(SC2^4 f1^4 f2^2)
//      sigma = f0 * f1^(1/2) * f2^(1/4) * ff^(1/8);   out = K0 / sigma
//
// Round 3: FFMA2 (fma.rn.f32x2) packed math with pre-duplicated A smem planes,
// Hermitian 6-of-9-tile gram with mirrored writes, parallel f0, phase table.
// ---------------------------------------------------------------------------

#define CDIM 192
#define MAT (CDIM*CDIM)          // 36864
#define NW 145                   // unique frequencies (conjugate symmetry)
#define NTOT2 289.0              // 17*17
#define SC2 48.0                 // pre-scale^2 applied to A (keeps eigs ~O(1))
#define NTILE 6                  // Hermitian: 3 diag + 3 upper tiles
#define NPART (NTILE*NW)         // 870
#define F0BLK 256

typedef unsigned long long ull;

__device__ double g_f0sq;
__device__ double g_f0part[F0BLK];
__device__ double g_part[3][NPART];
__device__ double g_inv_sigma;
__device__ float2 g_phase[NW * 9];
__device__ float2 g_bufA[NW * MAT];   // A, then G2
__device__ float2 g_bufB[NW * MAT];   // G1, then G4

__device__ __forceinline__ ull pack2(float lo, float hi) {
    ull r; asm("mov.b64 %0, {%1, %2};" : "=l"(r) : "f"(lo), "f"(hi)); return r;
}
__device__ __forceinline__ void unpack2(ull v, float& lo, float& hi) {
    asm("mov.b64 {%0, %1}, %2;" : "=f"(lo), "=f"(hi) : "l"(v));
}
__device__ __forceinline__ void ffma2(ull& d, ull a, ull b) {
    asm("fma.rn.f32x2 %0, %1, %2, %3;" : "=l"(d) : "l"(a), "l"(b), "l"(d));
}

// ---- ||K0||_F^2 partials: 256 blocks, deterministic per-block range --------
__global__ void k_f0a(const float* __restrict__ K0, int n) {
    __shared__ double sred[256];
    int per = (n + F0BLK - 1) / F0BLK;          // 1296 for n=331776
    int base = blockIdx.x * per;
    int end = min(base + per, n);
    double s = 0.0;
    for (int i = base + threadIdx.x; i < end; i += 256) {
        float v = K0[i];
        s += (double)v * (double)v;
    }
    sred[threadIdx.x] = s;
    __syncthreads();
    for (int off = 128; off > 0; off >>= 1) {
        if (threadIdx.x < off) sred[threadIdx.x] += sred[threadIdx.x + off];
        __syncthreads();
    }
    if (threadIdx.x == 0) g_f0part[blockIdx.x] = sred[0];
}

// ---- combine f0 + build phase table (fp64 trig done once) ------------------
__global__ void k_f0b() {
    __shared__ double sred[256];
    __shared__ double s_scale;
    sred[threadIdx.x] = g_f0part[threadIdx.x];
    __syncthreads();
    for (int off = 128; off > 0; off >>= 1) {
        if (threadIdx.x < off) sred[threadIdx.x] += sred[threadIdx.x + off];
        __syncthreads();
    }
    if (threadIdx.x == 0) {
        g_f0sq = sred[0];
        s_scale = sqrt(SC2 / sred[0]);
    }
    __syncthreads();
    double sc = s_scale;
    for (int idx = threadIdx.x; idx < NW * 9; idx += 256) {
        int w = idx / 9, s = idx % 9;
        int u, v;
        if (w == 0)      { u = 0; v = 0; }
        else if (w <= 8) { u = 0; v = w; }
        else             { u = 1 + (w - 9) / 17; v = (w - 9) % 17; }
        int y = s / 3, x = s % 3;
        int m = (u * y + v * x) % 17;
        double ang = -2.0 * 3.14159265358979323846 * (double)m / 17.0;
        g_phase[idx] = make_float2((float)(cos(ang) * sc), (float)(sin(ang) * sc));
    }
}

// ---- Build A(w) = scaled DFT of K0 ----------------------------------------
// grid (144, 145), block 256.
__global__ void k_build(const float* __restrict__ K0) {
    int w = blockIdx.y;
    __shared__ float2 ph[9];
    if (threadIdx.x < 9) ph[threadIdx.x] = g_phase[w * 9 + threadIdx.x];
    __syncthreads();
    int idx = blockIdx.x * 256 + threadIdx.x;
    const float* kp = K0 + idx * 9;
    float re = 0.f, im = 0.f;
#pragma unroll
    for (int s = 0; s < 9; s++) {
        float k = kp[s];
        re = fmaf(k, ph[s].x, re);
        im = fmaf(k, ph[s].y, im);
    }
    g_bufA[w * MAT + idx] = make_float2(re, im);
}

// ---- Batched Hermitian gram: Y = X^H X (192x192 complex per freq) ---------
// stage 0: A->G1 (A->B), 1: G1->G2 (B->A), 2: G2->G4 (A->B)
// grid (6, 145): 6 tiles (3 diag + 3 upper); lower tiles written by conjugate
// mirror. block 256, 64x64 complex tile, 4x4 complex cells per thread.
__global__ void __launch_bounds__(256) k_gram(int stage) {
    const float2* __restrict__ src = (stage == 1) ? g_bufB : g_bufA;
    float2* __restrict__ dst       = (stage == 1) ? g_bufA : g_bufB;

    int w = blockIdx.y;
    const float2* X = src + w * MAT;
    float2* Y       = dst + w * MAT;

    int t = blockIdx.x;            // (ai,bi): (0,0)(0,1)(0,2)(1,1)(1,2)(2,2)
    int ai, bi;
    if (t < 3)      { ai = 0; bi = t; }
    else if (t < 5) { ai = 1; bi = t - 2; }
    else            { ai = 2; bi = 2; }
    int a0 = ai * 64, b0 = bi * 64;

    __shared__ ull sAxx[16][64];   // (ax,ax) duplicated
    __shared__ ull sAyy[16][64];   // (ay,ay) duplicated
    __shared__ ull sB[16][64];     // (bx,by) raw

    int tx = threadIdx.x & 15;
    int ty = (threadIdx.x >> 4) & 15;

    ull P[4][4], Q[4][4];
#pragma unroll
    for (int i = 0; i < 4; i++)
#pragma unroll
        for (int j = 0; j < 4; j++) { P[i][j] = 0ULL; Q[i][j] = 0ULL; }

    int lc = threadIdx.x & 63;
    int lr = threadIdx.x >> 6;

    for (int kc = 0; kc < CDIM; kc += 16) {
#pragma unroll
        for (int rr = 0; rr < 4; rr++) {
            int r = lr + rr * 4;
            float2 va = X[(kc + r) * CDIM + a0 + lc];
            float2 vb = X[(kc + r) * CDIM + b0 + lc];
            sAxx[r][lc] = pack2(va.x, va.x);
            sAyy[r][lc] = pack2(va.y, va.y);
            sB[r][lc]   = pack2(vb.x, vb.y);
        }
        __syncthreads();
#pragma unroll
        for (int kk = 0; kk < 16; kk++) {
            ull bv[4];
#pragma unroll
            for (int j = 0; j < 4; j++) bv[j] = sB[kk][tx + 16 * j];
#pragma unroll
            for (int i = 0; i < 4; i++) {
                ull axx = sAxx[kk][ty + 16 * i];
                ull ayy = sAyy[kk][ty + 16 * i];
#pragma unroll
                for (int j = 0; j < 4; j++) {
                    ffma2(P[i][j], axx, bv[j]);   // (+ax*bx, +ax*by)
                    ffma2(Q[i][j], ayy, bv[j]);   // (+ay*bx, +ay*by)
                }
            }
        }
        __syncthreads();
    }

    bool offdiag = (ai != bi);
    float ns = 0.f;
#pragma unroll
    for (int i = 0; i < 4; i++)
#pragma unroll
        for (int j = 0; j < 4; j++) {
            float px, py, qx, qy;
            unpack2(P[i][j], px, py);
            unpack2(Q[i][j], qx, qy);
            float r  = px + qy;        // ax*bx + ay*by
            float im = py - qx;        // ax*by - ay*bx
            int ga = a0 + ty + 16 * i;
            int gb = b0 + tx + 16 * j;
            Y[ga * CDIM + gb] = make_float2(r, im);
            if (offdiag) Y[gb * CDIM + ga] = make_float2(r, -im);
            ns = fmaf(r, r, ns);
            ns = fmaf(im, im, ns);
        }

    __shared__ double sred[256];
    sred[threadIdx.x] = (double)ns;
    __syncthreads();
    for (int off = 128; off > 0; off >>= 1) {
        if (threadIdx.x < off) sred[threadIdx.x] += sred[threadIdx.x + off];
        __syncthreads();
    }
    if (threadIdx.x == 0) {
        double wgt = ((w == 0) ? 1.0 : 2.0) * (offdiag ? 2.0 : 1.0);
        g_part[stage][w * NTILE + t] = wgt * sred[0];
    }
}

// ---- Deterministic final reduction + sigma ---------------------------------
__global__ void k_sigma() {
    __shared__ double sred[256];
    double m[3];
    for (int s = 0; s < 3; s++) {
        double acc = 0.0;
        for (int i = threadIdx.x; i < NPART; i += 256) acc += g_part[s][i];
        sred[threadIdx.x] = acc;
        __syncthreads();
        for (int off = 128; off > 0; off >>= 1) {
            if (threadIdx.x < off) sred[threadIdx.x] += sred[threadIdx.x + off];
            __syncthreads();
        }
        m[s] = sred[0];
        __syncthreads();
    }
    if (threadIdx.x == 0) {
        double f0 = sqrt(g_f0sq);
        double f1 = sqrt(m[0] / NTOT2) / SC2;
        double f2 = sqrt(m[1] / NTOT2) / (SC2 * SC2 * f1 * f1);
        double ff = sqrt(m[2] / NTOT2) /
                    (SC2 * SC2 * SC2 * SC2 * f1 * f1 * f1 * f1 * f2 * f2);
        double logs = log(f0) + 0.5 * log(f1) + 0.25 * log(f2) + 0.125 * log(ff);
        g_inv_sigma = exp(-logs);
    }
}

__global__ void k_scale(const float* __restrict__ K0, float* __restrict__ out,
                        int n) {
    float s = (float)g_inv_sigma;
    int i = blockIdx.x * 256 + threadIdx.x;
    if (i < n) out[i] = K0[i] * s;
}

extern "C" void kernel_launch(void* const* d_in, const int* in_sizes, int n_in,
                              void* d_out, int out_size) {
    const float* K0 = (const float*)d_in[0];
    float* out = (float*)d_out;
    int n = in_sizes[0];   // 331776

    k_f0a<<<F0BLK, 256>>>(K0, n);
    k_f0b<<<1, 256>>>();
    k_build<<<dim3(144, NW), 256>>>(K0);
    k_gram<<<dim3(NTILE, NW), 256>>>(0);
    k_gram<<<dim3(NTILE, NW), 256>>>(1);
    k_gram<<<dim3(NTILE, NW), 256>>>(2);
    k_sigma<<<1, 256>>>();
    k_scale<<<(n + 255) / 256, 256>>>(K0, out, n);
}